// round 3
// baseline (speedup 1.0000x reference)
#include <cuda_runtime.h>
#include <cstdint>

#define BB 4
#define SS 2048
#define DD 768
#define NH 4
#define DH 192
#define KW 4
#define G4 4
#define EPSV 1e-5f
#define CL 8            // cluster size (CTAs per chain)
#define ESL 24          // e-slice per CTA = DH/CL

typedef unsigned long long u64t;

// Scratch (device globals -- no allocation allowed)
__device__ float g_xconv[BB*SS*DD];               // 25 MB
__device__ float g_gates[BB*NH*SS*G4*DH];         // 100 MB  [b][h][s][g][e]
__device__ float g_y[BB*NH*SS*DH];                // 25 MB   [b][h][s][e]

#define FMA2(d, a, b, c) \
    asm("fma.rn.f32x2 %0, %1, %2, %3;" : "=l"(d) : "l"(a), "l"(b), "l"(c))

__device__ __forceinline__ u64t pack2(float lo, float hi) {
    return ((u64t)__float_as_uint(hi) << 32) | (u64t)__float_as_uint(lo);
}

// ---------------------------------------------------------------------------
// Kernel 1: causal depthwise conv (K=4) + swish
// ---------------------------------------------------------------------------
__global__ void conv_swish_kernel(const float* __restrict__ x,
                                  const float* __restrict__ ck,
                                  const float* __restrict__ cb) {
    int idx = blockIdx.x * blockDim.x + threadIdx.x;     // per float4
    const int D4 = DD / 4;
    if (idx >= BB * SS * D4) return;
    int c4 = idx % D4;
    int s  = (idx / D4) % SS;
    int b  = idx / (SS * D4);

    float4 acc = *(const float4*)&cb[c4 * 4];
    const float4* x4 = (const float4*)x;
#pragma unroll
    for (int j = 0; j < KW; j++) {
        int sj = s - (KW - 1) + j;
        if (sj >= 0) {
            float4 xv = x4[(b * SS + sj) * D4 + c4];
            float4 kv = *(const float4*)&ck[j * DD + c4 * 4];
            acc.x = fmaf(xv.x, kv.x, acc.x);
            acc.y = fmaf(xv.y, kv.y, acc.y);
            acc.z = fmaf(xv.z, kv.z, acc.z);
            acc.w = fmaf(xv.w, kv.w, acc.w);
        }
    }
    acc.x = acc.x / (1.f + __expf(-acc.x));
    acc.y = acc.y / (1.f + __expf(-acc.y));
    acc.z = acc.z / (1.f + __expf(-acc.z));
    acc.w = acc.w / (1.f + __expf(-acc.w));
    ((float4*)g_xconv)[idx] = acc;
}

// ---------------------------------------------------------------------------
// Kernel 2: gate pre-activation GEMMs (packed f32x2 FMAs)
// ---------------------------------------------------------------------------
__global__ __launch_bounds__(256)
void gate_gemm_kernel(const float* __restrict__ x,
                      const float* __restrict__ Wi, const float* __restrict__ Wf,
                      const float* __restrict__ Wz, const float* __restrict__ Wo,
                      const float* __restrict__ cbias) {
    int hg = blockIdx.y;
    int h = hg >> 2;
    int g = hg & 3;
    const float* A = (g < 2) ? g_xconv : x;
    const float* W = (g == 0) ? Wi : (g == 1) ? Wf : (g == 2) ? Wz : Wo;
    W += h * DH * DH;
    int row0 = blockIdx.x * 128;

    __shared__ __align__(16) float As[16][128];
    __shared__ __align__(16) float Ws[16][DH];

    int tid = threadIdx.x;
    int tr = tid >> 4;
    int tc = tid & 15;

    u64t acc2[8][6];
#pragma unroll
    for (int i = 0; i < 8; i++)
#pragma unroll
        for (int j = 0; j < 6; j++) acc2[i][j] = 0ull;

    for (int k0 = 0; k0 < DH; k0 += 16) {
#pragma unroll
        for (int i = 0; i < 2; i++) {
            int lidx = tid + i * 256;
            int r  = lidx >> 2;
            int kk = (lidx & 3) * 4;
            int grow = row0 + r;
            float4 v = *(const float4*)&A[grow * DD + h * DH + k0 + kk];
            As[kk + 0][r] = v.x; As[kk + 1][r] = v.y;
            As[kk + 2][r] = v.z; As[kk + 3][r] = v.w;
        }
#pragma unroll
        for (int i = 0; i < 3; i++) {
            int lidx = tid + i * 256;
            int kr = lidx / 48;
            int c4 = lidx % 48;
            float4 v = *(const float4*)&W[(k0 + kr) * DH + c4 * 4];
            *(float4*)&Ws[kr][c4 * 4] = v;
        }
        __syncthreads();
#pragma unroll
        for (int kk = 0; kk < 16; kk++) {
            float a[8];
#pragma unroll
            for (int i = 0; i < 8; i += 4) {
                float4 v = *(const float4*)&As[kk][tr * 8 + i];
                a[i] = v.x; a[i + 1] = v.y; a[i + 2] = v.z; a[i + 3] = v.w;
            }
            u64t bp[6];
            const ulonglong2* wrow = (const ulonglong2*)&Ws[kk][tc * 12];
#pragma unroll
            for (int m = 0; m < 3; m++) {
                ulonglong2 v = wrow[m];
                bp[2 * m] = v.x; bp[2 * m + 1] = v.y;
            }
#pragma unroll
            for (int i = 0; i < 8; i++) {
                u64t ai = pack2(a[i], a[i]);
#pragma unroll
                for (int m = 0; m < 6; m++)
                    FMA2(acc2[i][m], ai, bp[m], acc2[i][m]);
            }
        }
        __syncthreads();
    }

#pragma unroll
    for (int i = 0; i < 8; i++) {
        int grow = row0 + tr * 8 + i;
        int b = grow >> 11;
        int s = grow & 2047;
        long base = (long)((b * NH + h) * SS + s) * (G4 * DH) + g * DH + tc * 12;
#pragma unroll
        for (int m = 0; m < 6; m++) {
            float lo = __uint_as_float((unsigned)(acc2[i][m] & 0xffffffffull));
            float hi = __uint_as_float((unsigned)(acc2[i][m] >> 32));
            g_gates[base + 2 * m]     = lo + cbias[g * DD + h * DH + tc * 12 + 2 * m];
            g_gates[base + 2 * m + 1] = hi + cbias[g * DD + h * DH + tc * 12 + 2 * m + 1];
        }
    }
}

// ---------------------------------------------------------------------------
// Kernel 3: sequential sLSTM scan — e-sliced cluster topology.
//   16 chains x 8 CTAs (cluster 8). CTA rank r computes ALL 4 gates for
//   e-slice [24r, 24r+24), full d. Only h (192 floats) is exchanged per step
//   via st.async multicast (768 B in/out per CTA). Gate state (c,n,m) lives
//   in the registers of threads t<24. Double-buffered h + tx-mbarriers.
// ---------------------------------------------------------------------------
__device__ __forceinline__ uint32_t smem_u32(const void* p) {
    uint32_t a;
    asm("{ .reg .u64 t; cvta.to.shared.u64 t, %1; cvt.u32.u64 %0, t; }"
        : "=r"(a) : "l"(p));
    return a;
}

__global__ void __cluster_dims__(CL, 1, 1) __launch_bounds__(384, 1)
scan_kernel(const float* __restrict__ R) {
    int rank  = blockIdx.x & (CL - 1);
    int chain = blockIdx.x / CL;       // b*NH + h
    int h = chain & 3;

    __shared__ __align__(16) float h_buf[2][DH];
    __shared__ float red[384];
    __shared__ float pre_sm[96];
    __shared__ __align__(8) u64t mbar[2];

    int t = threadIdx.x;
    int o = t % 96;                    // output index: g*24 + e_loc
    int p = t / 96;                    // d-quarter 0..3
    int g = o / ESL;
    int e_loc = o % ESL;
    int e = rank * ESL + e_loc;

    // Weights: thread holds R[g][h][48p+j][e], j=0..47, as 24 f32x2 pairs
    u64t w2[24];
    {
        const float* Rb = R + (long)((g * NH + h) * DH) * DH + e;
        int d0 = p * 48;
#pragma unroll
        for (int j = 0; j < 24; j++)
            w2[j] = pack2(Rb[(d0 + 2 * j) * DH], Rb[(d0 + 2 * j + 1) * DH]);
    }

    if (t < DH) { h_buf[0][t] = 0.f; h_buf[1][t] = 0.f; }
    if (t == 0) {
        asm volatile("mbarrier.init.shared.b64 [%0], 1;" :: "r"(smem_u32(&mbar[0])) : "memory");
        asm volatile("mbarrier.init.shared.b64 [%0], 1;" :: "r"(smem_u32(&mbar[1])) : "memory");
    }
    __syncthreads();
    asm volatile("barrier.cluster.arrive.aligned;" ::: "memory");
    asm volatile("barrier.cluster.wait.aligned;" ::: "memory");

    // Pre-arm both buffers: 8 CTAs x 24 floats = 768 bytes per phase
    if (t == 0) {
        asm volatile("mbarrier.arrive.expect_tx.shared.b64 _, [%0], %1;"
                     :: "r"(smem_u32(&mbar[0])), "r"(768u) : "memory");
        asm volatile("mbarrier.arrive.expect_tx.shared.b64 _, [%0], %1;"
                     :: "r"(smem_u32(&mbar[1])), "r"(768u) : "memory");
    }

    // Hoisted remote addresses for the gating threads (t<24): h slot + mbar
    uint32_t ra[CL], rb[CL];
    {
        uint32_t lh  = smem_u32(&h_buf[0][rank * ESL + (t % ESL)]);
        uint32_t lmb = smem_u32(&mbar[0]);
#pragma unroll
        for (int r = 0; r < CL; r++) {
            asm("mapa.shared::cluster.u32 %0, %1, %2;" : "=r"(ra[r]) : "r"(lh), "r"(r));
            asm("mapa.shared::cluster.u32 %0, %1, %2;" : "=r"(rb[r]) : "r"(lmb), "r"(r));
        }
    }

    // Gate preactivation stream for this thread's (g, e)
    const float* Gp = g_gates + (long)(chain * SS) * (G4 * DH) + g * DH + e;
    float gcur = (t < 96) ? Gp[0] : 0.f;

    float* Yp = g_y + ((long)chain * SS + 0) * DH + rank * ESL;

    // Per-element state in registers (threads t<24)
    float c_st = 0.f, n_st = 0.f, m_st = 0.f;
    int ph0 = 0, ph1 = 0;

    for (int step = 0; step < SS; step++) {
        int buf  = step & 1;
        int nbuf = buf ^ 1;

        // --- matvec: part = sum_{d in quarter p} h[d] * R[d][e]  (24 FMA2)
        u64t acc0 = 0ull, acc1 = 0ull;
        const ulonglong2* h2v = (const ulonglong2*)(h_buf[buf] + p * 48);
#pragma unroll
        for (int jj = 0; jj < 12; jj++) {
            ulonglong2 hv = h2v[jj];
            FMA2(acc0, w2[2 * jj],     hv.x, acc0);
            FMA2(acc1, w2[2 * jj + 1], hv.y, acc1);
        }
        float s0 = __uint_as_float((unsigned)(acc0 & 0xffffffffull));
        float s1 = __uint_as_float((unsigned)(acc0 >> 32));
        float s2 = __uint_as_float((unsigned)(acc1 & 0xffffffffull));
        float s3 = __uint_as_float((unsigned)(acc1 >> 32));
        red[t] = (s0 + s1) + (s2 + s3);
        __syncthreads();

        if (t < 96) {
            pre_sm[t] = (red[t] + red[t + 96]) + (red[t + 192] + red[t + 288]) + gcur;
            if (step + 1 < SS) gcur = Gp[(long)(step + 1) * (G4 * DH)];
        }
        __syncthreads();

        if (t < ESL) {
            float iv = pre_sm[t];
            float fv = pre_sm[ESL + t];
            float zv = pre_sm[2 * ESL + t];
            float ov = pre_sm[3 * ESL + t];
            float mn = fmaxf(fv + m_st, iv);
            float ia = __expf(iv - mn);
            float fa = __expf(fv + m_st - mn);
            float tz = __expf(2.f * zv);
            float tanhz = 1.f - __fdividef(2.f, tz + 1.f);
            float cn = fmaf(ia, tanhz, fa * c_st);
            float nn = fmaf(fa, n_st, ia);
            float sig = __fdividef(1.f, 1.f + __expf(-ov));
            float hn = sig * __fdividef(cn, nn);
            c_st = cn; n_st = nn; m_st = mn;
            Yp[(long)step * DH + t] = hn;

            uint32_t hofs = (uint32_t)nbuf * (DH * 4);
            uint32_t mofs = (uint32_t)nbuf * 8;
#pragma unroll
            for (int r = 0; r < CL; r++) {
                asm volatile(
                    "st.async.shared::cluster.mbarrier::complete_tx::bytes.f32 [%0], %1, [%2];"
                    :: "r"(ra[r] + hofs), "f"(hn), "r"(rb[r] + mofs) : "memory");
            }
        }

        // wait for full h_{step+1} (768 bytes from 8 CTAs)
        {
            uint32_t mb = smem_u32(&mbar[0]) + (uint32_t)nbuf * 8;
            int ph = nbuf ? ph1 : ph0;
            asm volatile(
                "{\n\t"
                ".reg .pred P1;\n\t"
                "WAIT_%=:\n\t"
                "mbarrier.try_wait.parity.acquire.cta.shared::cta.b64 P1, [%0], %1, 0x989680;\n\t"
                "@P1 bra.uni DONE_%=;\n\t"
                "bra.uni WAIT_%=;\n\t"
                "DONE_%=:\n\t"
                "}"
                :: "r"(mb), "r"(ph) : "memory");
            if (nbuf) ph1 ^= 1; else ph0 ^= 1;
            if (t == 0) {
                asm volatile("mbarrier.arrive.expect_tx.shared.b64 _, [%0], %1;"
                             :: "r"(mb), "r"(768u) : "memory");
            }
        }
    }
}

// ---------------------------------------------------------------------------
// Kernel 4: per-head layernorm + scale, reorder to (B,S,D)
// ---------------------------------------------------------------------------
__global__ void ln_kernel(const float* __restrict__ gn, float* __restrict__ out) {
    int gtid = blockIdx.x * blockDim.x + threadIdx.x;
    int warp = gtid >> 5;
    int lane = gtid & 31;
    if (warp >= BB * NH * SS) return;

    int s = warp % SS;
    int chain = warp / SS;
    int b = chain >> 2;
    int h = chain & 3;

    const float* y = g_y + (long)warp * DH;
    float v[6];
    float sum = 0.f, sq = 0.f;
#pragma unroll
    for (int k = 0; k < 6; k++) {
        v[k] = y[lane + 32 * k];
        sum += v[k];
        sq  = fmaf(v[k], v[k], sq);
    }
#pragma unroll
    for (int o = 16; o > 0; o >>= 1) {
        sum += __shfl_xor_sync(0xffffffffu, sum, o);
        sq  += __shfl_xor_sync(0xffffffffu, sq, o);
    }
    float mu  = sum * (1.f / DH);
    float var = sq * (1.f / DH) - mu * mu;
    float inv = rsqrtf(var + EPSV);

    long obase = (long)(b * SS + s) * DD + h * DH;
#pragma unroll
    for (int k = 0; k < 6; k++) {
        int ei = lane + 32 * k;
        out[obase + ei] = (v[k] - mu) * inv * gn[h * DH + ei];
    }
}

// ---------------------------------------------------------------------------
extern "C" void kernel_launch(void* const* d_in, const int* in_sizes, int n_in,
                              void* d_out, int out_size) {
    const float* x     = (const float*)d_in[0];
    const float* ck    = (const float*)d_in[1];
    const float* cb    = (const float*)d_in[2];
    const float* Wi    = (const float*)d_in[3];
    const float* Wf    = (const float*)d_in[4];
    const float* Wz    = (const float*)d_in[5];
    const float* Wo    = (const float*)d_in[6];
    const float* R     = (const float*)d_in[7];
    const float* cbias = (const float*)d_in[8];
    const float* gn    = (const float*)d_in[9];
    float* out = (float*)d_out;

    {
        int total = BB * SS * (DD / 4);
        conv_swish_kernel<<<(total + 255) / 256, 256>>>(x, ck, cb);
    }
    {
        dim3 grid(BB * SS / 128, NH * G4);
        gate_gemm_kernel<<<grid, 256>>>(x, Wi, Wf, Wz, Wo, cbias);
    }
    scan_kernel<<<BB * NH * CL, 384>>>(R);
    {
        int warps = BB * NH * SS;
        int threads = warps * 32;
        ln_kernel<<<(threads + 255) / 256, 256>>>(gn, out);
    }
    (void)in_sizes; (void)n_in; (void)out_size;
}